// round 7
// baseline (speedup 1.0000x reference)
#include <cuda_runtime.h>
#include <stdint.h>

// BackEdgeConv2d: out = x * !(5 <= boxcount7x7(x >= 128/255, reflect-pad) <= 19)
// Vertical-first streaming byte-SWAR box filter, 4 rows per barrier:
//   [4x: prefetch / binarize / vsum / publish vrow] -> bar -> [4x: hsum / mask / store]

static constexpr int W     = 1024;
static constexpr int HB    = 32;           // output rows per block
static constexpr int WORDS = W / 4;        // 256 words of 4 pixels
static constexpr int U     = 4;            // rows per barrier group

// bits of float32(128/255) = 0x3F008081; K = thresh-1 (sign trick, x >= 0)
static constexpr uint32_t KTH = 0x3F008081u - 1u;

__device__ __forceinline__ uint32_t prmt(uint32_t a, uint32_t b, uint32_t s)
{
    uint32_t d;
    asm("prmt.b32 %0, %1, %2, %3;" : "=r"(d) : "r"(a), "r"(b), "r"(s));
    return d;
}

// 4 floats -> packed 0/1 bytes (byte i = pixel 4t+i >= thresh)
__device__ __forceinline__ uint32_t binz(uint4 v)
{
    uint32_t s0 = KTH - v.x, s1 = KTH - v.y, s2 = KTH - v.z, s3 = KTH - v.w;
    uint32_t p01 = prmt(s0, s1, 0x00FB);   // (sgn0, sgn1, 0, 0)
    uint32_t p23 = prmt(s2, s3, 0x00FB);
    return prmt(p01, p23, 0x5410) & 0x01010101u;
}

__device__ __forceinline__ int refl(int g)
{
    g = (g < 0) ? -g : g;
    return (g > W - 1) ? (2 * (W - 1) - g) : g;
}

__global__ void __launch_bounds__(256)
backedge_kernel(const uint4* __restrict__ x, uint4* __restrict__ out)
{
    __shared__ uint32_t ring[8][WORDS];      // thread-private binary ring (8KB)
    __shared__ uint32_t vrow[2 * U][WORDS + 4]; // two groups of 4 vsum rows (~8.3KB)

    const int t  = threadIdx.x;              // word column 0..255
    const int y0 = blockIdx.x * HB;
    const size_t off = (size_t)blockIdx.y * (size_t)W * WORDS;
    const uint4* __restrict__ xi = x + off;
    uint4* __restrict__ xo = out + off;

    // ---- warm-up: padded rows 0..5 (image rows y0-3 .. y0+2), 1-deep prefetch ----
    uint32_t vsum = 0;
    uint4 pv = xi[(size_t)refl(y0 - 3) * WORDS + t];
    #pragma unroll
    for (int r = 0; r < 6; ++r) {
        uint4 cur = pv;
        pv = xi[(size_t)refl(y0 - 2 + r) * WORDS + t];   // padded row r+1
        uint32_t b = binz(cur);
        vsum += b;
        ring[r][t] = b;
    }
    // pv = padded row 6 (image y0+3)

    int grp = 0;
    for (int y = 0; y < HB; y += U) {
        // -------- phase A: 4 rows of binarize + vertical slide --------
        #pragma unroll
        for (int j = 0; j < U; ++j) {
            uint4 cur = pv;                               // padded row y+j+6
            if (y + j + 1 < HB)                           // prefetch padded row y+j+7
                pv = xi[(size_t)refl(y0 + 4 + y + j) * WORDS + t];
            uint32_t b = binz(cur);
            vsum += b;                                    // rows (y+j)-3..(y+j)+3, bytes <= 7
            ring[(y + j + 6) & 7][t] = b;

            vrow[grp + j][1 + t] = vsum;
            if (t == 0)        // pixels -4..-1: byte0 unused, (v3,v2,v1) in bytes 1..3
                vrow[grp + j][0]   = prmt(vsum, vsum, 0x1234);
            else if (t == 255) // pixels 1024..: (v1022,v1021,v1020), byte3 unused
                vrow[grp + j][257] = prmt(vsum, vsum, 0x0012);

            vsum -= ring[(y + j) & 7][t];                 // drop row (y+j)-3
        }
        __syncthreads();

        // -------- phase B: 4 rows of horizontal 7-tap + mask + store --------
        #pragma unroll
        for (int j = 0; j < U; ++j) {
            uint32_t A = vrow[grp + j][t];
            uint32_t B = vrow[grp + j][t + 1];
            uint32_t C = vrow[grp + j][t + 2];
            uint32_t c = B
                + __funnelshift_r(A, B, 8)  + __funnelshift_r(A, B, 16) + __funnelshift_r(A, B, 24)
                + __funnelshift_r(B, C, 8)  + __funnelshift_r(B, C, 16) + __funnelshift_r(B, C, 24);

            // mask byte = 0x80 where 5 <= c <= 19 (c <= 49, no carries)
            uint32_t m = (c + 0x7B7B7B7Bu) & (0x93939393u - c) & 0x80808080u;

            uint4 xv = xi[(size_t)(y0 + y + j) * WORDS + t];  // L1/L2-hot reload
            uint4 o;
            o.x = xv.x & ~prmt(m, m, 0x8888);   // sign-replicate byte k -> 0xFFFFFFFF/0
            o.y = xv.y & ~prmt(m, m, 0x9999);
            o.z = xv.z & ~prmt(m, m, 0xAAAA);
            o.w = xv.w & ~prmt(m, m, 0xBBBB);
            xo[(size_t)(y0 + y + j) * WORDS + t] = o;
        }
        grp ^= U;   // double-buffer the vrow group; one barrier per group is race-free
    }
}

extern "C" void kernel_launch(void* const* d_in, const int* in_sizes, int n_in,
                              void* d_out, int out_size)
{
    const uint4* x = (const uint4*)d_in[0];
    uint4* o = (uint4*)d_out;
    const int nimg = in_sizes[0] / (W * W);   // 48 planes
    dim3 grid(W / HB, nimg);
    backedge_kernel<<<grid, 256>>>(x, o);
}

// round 9
// speedup vs baseline: 1.0055x; 1.0055x over previous
#include <cuda_runtime.h>
#include <stdint.h>

// BackEdgeConv2d: out = x * !(5 <= boxcount7x7(x >= 128/255, reflect-pad) <= 19)
// Barrier-free warp-autonomous strips. Per lane: one 4-px word column.
// Vertical 7-row sliding sum via 2-register bit-history (no smem ring);
// horizontal 7-tap via shfl + funnel-shift byte-SWAR. Zero shared memory.

static constexpr int W     = 1024;
static constexpr int HB    = 32;           // output rows per block
static constexpr int WORDS = W / 4;        // 256 words per row

// bits of float32(128/255) = 0x3F008081; K = thresh-1 (sign trick, x >= 0)
static constexpr uint32_t KTH = 0x3F008081u - 1u;

__device__ __forceinline__ uint32_t prmt(uint32_t a, uint32_t b, uint32_t s)
{
    uint32_t d;
    asm("prmt.b32 %0, %1, %2, %3;" : "=r"(d) : "r"(a), "r"(b), "r"(s));
    return d;
}

// 4 floats -> packed 0/1 bytes (byte i = pixel 4t+i >= thresh)
__device__ __forceinline__ uint32_t binz(uint4 v)
{
    uint32_t s0 = KTH - v.x, s1 = KTH - v.y, s2 = KTH - v.z, s3 = KTH - v.w;
    uint32_t p01 = prmt(s0, s1, 0x00FB);   // (sgn0, sgn1, -, -)
    uint32_t p23 = prmt(s2, s3, 0x00FB);
    return prmt(p01, p23, 0x5410) & 0x01010101u;
}

__device__ __forceinline__ int refl(int g)
{
    g = (g < 0) ? -g : g;
    return (g > W - 1) ? (2 * (W - 1) - g) : g;
}

template<bool EDGE>
__device__ __forceinline__ void run_band(
    const uint4* __restrict__ xi, uint4* __restrict__ xo,
    int y0, int w_idx, int l_idx, bool active, bool ledge, bool redge)
{
    // ---- warm-up: image rows y0-3 .. y0+2 into (vsum, hist) ----
    uint32_t hist = 0, vsum = 0;
    int g0 = EDGE ? refl(y0 - 3) : (y0 - 3);
    uint4 pv = xi[(size_t)g0 * WORDS + l_idx];
    #pragma unroll
    for (int r = 0; r < 6; ++r) {
        uint4 cur = pv;
        int g = EDGE ? refl(y0 - 2 + r) : (y0 - 2 + r);
        pv = xi[(size_t)g * WORDS + l_idx];
        uint32_t b = binz(cur);
        vsum += b;                          // bytes <= 6
        hist  = (hist << 1) | b;            // bit k = row (y0+2-k-? ) history
    }
    // pv = image row y0+3

    for (int y = 0; y < HB; ++y) {
        uint4 cur = pv;                     // image row y0+y+3
        if (y + 1 < HB) {
            int g = EDGE ? refl(y0 + 4 + y) : (y0 + 4 + y);
            pv = xi[(size_t)g * WORDS + l_idx];
        }
        uint32_t b = binz(cur);
        hist = ((hist << 1) | b) & 0x7F7F7F7Fu;  // bit k = row y0+y+3-k, k=0..6
        vsum += b;                               // rows y0+y-3 .. y0+y+3, bytes <= 7

        // horizontal neighbors via shfl (lane l-1 / l+1 hold words p-1 / p+1)
        uint32_t A = __shfl_up_sync(0xFFFFFFFFu, vsum, 1);
        uint32_t C = __shfl_down_sync(0xFFFFFFFFu, vsum, 1);
        if (ledge) A = prmt(vsum, vsum, 0x1234); // reflect: (-, v3, v2, v1)
        if (redge) C = prmt(vsum, vsum, 0x0012); // reflect: (v2, v1, v0, -)
        uint32_t B = vsum;
        uint32_t c = B
            + __funnelshift_r(A, B, 8)  + __funnelshift_r(A, B, 16) + __funnelshift_r(A, B, 24)
            + __funnelshift_r(B, C, 8)  + __funnelshift_r(B, C, 16) + __funnelshift_r(B, C, 24);

        // mask byte = 0x80 where 5 <= c <= 19 (c <= 49, no carries)
        uint32_t m = (c + 0x7B7B7B7Bu) & (0x93939393u - c) & 0x80808080u;

        if (active) {
            uint4 xv = xi[(size_t)(y0 + y) * WORDS + w_idx];  // L1/L2-hot reload
            uint4 o;
            o.x = xv.x & ~prmt(m, m, 0x8888);   // sign-replicate byte k -> 0xFFFFFFFF/0
            o.y = xv.y & ~prmt(m, m, 0x9999);
            o.z = xv.z & ~prmt(m, m, 0xAAAA);
            o.w = xv.w & ~prmt(m, m, 0xBBBB);
            xo[(size_t)(y0 + y) * WORDS + w_idx] = o;
        }

        vsum -= (hist >> 6) & 0x01010101u;  // drop row y0+y-3 (bit 6 of hist)
    }
}

__global__ void __launch_bounds__(288, 6)
backedge_kernel(const uint4* __restrict__ x, uint4* __restrict__ out)
{
    const int lane = threadIdx.x & 31;
    const int warp = threadIdx.x >> 5;          // 0..8
    const int w_idx = warp * 30 + lane - 1;     // output word (-1..270)
    const int l_idx = min(max(w_idx, 0), WORDS - 1);  // clamped load word
    const bool active = (lane >= 1) && (lane <= 30) && (w_idx < WORDS);
    const bool ledge  = (w_idx == 0);
    const bool redge  = (w_idx == WORDS - 1);

    const int y0 = blockIdx.x * HB;
    const size_t off = (size_t)blockIdx.y * (size_t)W * WORDS;
    const uint4* __restrict__ xi = x + off;
    uint4* __restrict__ xo = out + off;

    // loads span rows y0-3 .. y0+HB+2
    if (y0 - 3 < 0 || y0 + HB + 2 > W - 1)
        run_band<true >(xi, xo, y0, w_idx, l_idx, active, ledge, redge);
    else
        run_band<false>(xi, xo, y0, w_idx, l_idx, active, ledge, redge);
}

extern "C" void kernel_launch(void* const* d_in, const int* in_sizes, int n_in,
                              void* d_out, int out_size)
{
    const uint4* x = (const uint4*)d_in[0];
    uint4* o = (uint4*)d_out;
    const int nimg = in_sizes[0] / (W * W);   // 48 planes
    dim3 grid(W / HB, nimg);
    backedge_kernel<<<grid, 288>>>(x, o);
}

// round 10
// speedup vs baseline: 1.0059x; 1.0004x over previous
#include <cuda_runtime.h>
#include <stdint.h>

// BackEdgeConv2d: out = x * !(5 <= boxcount7x7(x >= 128/255, reflect-pad) <= 19)
// Barrier-free warp-autonomous strips; 2-row groups with distance-2 batched
// prefetch (MLP=2 per warp), bit-history vertical window, shfl horizontal halos,
// streaming stores. Zero shared memory.

static constexpr int W     = 1024;
static constexpr int HB    = 32;           // output rows per block
static constexpr int WORDS = W / 4;        // 256 words per row

// bits of float32(128/255) = 0x3F008081; K = thresh-1 (sign trick, x >= 0)
static constexpr uint32_t KTH = 0x3F008081u - 1u;

__device__ __forceinline__ uint32_t prmt(uint32_t a, uint32_t b, uint32_t s)
{
    uint32_t d;
    asm("prmt.b32 %0, %1, %2, %3;" : "=r"(d) : "r"(a), "r"(b), "r"(s));
    return d;
}

// 4 floats -> packed 0/1 bytes (byte i = pixel >= thresh)
__device__ __forceinline__ uint32_t binz(uint4 v)
{
    uint32_t s0 = KTH - v.x, s1 = KTH - v.y, s2 = KTH - v.z, s3 = KTH - v.w;
    uint32_t p01 = prmt(s0, s1, 0x00FB);   // (sgn0, sgn1, -, -)
    uint32_t p23 = prmt(s2, s3, 0x00FB);
    return prmt(p01, p23, 0x5410) & 0x01010101u;
}

__device__ __forceinline__ int refl(int g)
{
    g = (g < 0) ? -g : g;
    return (g > W - 1) ? (2 * (W - 1) - g) : g;
}

template<bool EDGE>
__device__ __forceinline__ void run_band(
    const uint4* __restrict__ xi, uint4* __restrict__ xo,
    int y0, int w_idx, int l_idx, bool active, bool ledge, bool redge)
{
    auto row = [&](int g) -> int { return EDGE ? refl(g) : g; };

    // ---- warm-up: rows y0-3 .. y0+2 into (vsum, hist); 6 batched loads ----
    uint32_t hist = 0, vsum = 0;
    {
        uint4 r0 = xi[(size_t)row(y0 - 3) * WORDS + l_idx];
        uint4 r1 = xi[(size_t)row(y0 - 2) * WORDS + l_idx];
        uint4 r2 = xi[(size_t)row(y0 - 1) * WORDS + l_idx];
        uint4 r3 = xi[(size_t)row(y0    ) * WORDS + l_idx];
        uint4 r4 = xi[(size_t)row(y0 + 1) * WORDS + l_idx];
        uint4 r5 = xi[(size_t)row(y0 + 2) * WORDS + l_idx];
        uint32_t b;
        b = binz(r0); vsum += b; hist = (hist << 1) | b;
        b = binz(r1); vsum += b; hist = (hist << 1) | b;
        b = binz(r2); vsum += b; hist = (hist << 1) | b;
        b = binz(r3); vsum += b; hist = (hist << 1) | b;
        b = binz(r4); vsum += b; hist = (hist << 1) | b;
        b = binz(r5); vsum += b; hist = (hist << 1) | b;
    }
    // prefetched pair: rows y0+3, y0+4 (binarize inputs for outputs 0 and 1)
    uint4 pq0 = xi[(size_t)row(y0 + 3) * WORDS + l_idx];
    uint4 pq1 = xi[(size_t)row(y0 + 4) * WORDS + l_idx];

    for (int y = 0; y < HB; y += 2) {
        // front-batched prefetch for NEXT group (rows y+5, y+6 ahead of output y)
        uint4 nq0 = xi[(size_t)row(y0 + y + 5) * WORDS + l_idx];
        uint4 nq1 = xi[(size_t)row(y0 + y + 6) * WORDS + l_idx];

        #pragma unroll
        for (int j = 0; j < 2; ++j) {
            uint32_t b = binz(j == 0 ? pq0 : pq1);        // row y0+y+j+3
            hist = ((hist << 1) | b) & 0x7F7F7F7Fu;       // bit k = row y+j+3-k
            vsum += b;                                    // rows y+j-3..y+j+3, <= 7/byte

            uint32_t A = __shfl_up_sync(0xFFFFFFFFu, vsum, 1);
            uint32_t C = __shfl_down_sync(0xFFFFFFFFu, vsum, 1);
            if (ledge) A = prmt(vsum, vsum, 0x1234);      // reflect (-, v3, v2, v1)
            if (redge) C = prmt(vsum, vsum, 0x0012);      // reflect (v2, v1, v0, -)
            uint32_t B = vsum;
            uint32_t c = B
                + __funnelshift_r(A, B, 8)  + __funnelshift_r(A, B, 16) + __funnelshift_r(A, B, 24)
                + __funnelshift_r(B, C, 8)  + __funnelshift_r(B, C, 16) + __funnelshift_r(B, C, 24);

            // mask byte = 0x80 where 5 <= c <= 19 (c <= 49, no carries)
            uint32_t m = (c + 0x7B7B7B7Bu) & (0x93939393u - c) & 0x80808080u;

            if (active) {
                uint4 xv = xi[(size_t)(y0 + y + j) * WORDS + w_idx];  // L1/L2-hot
                uint4 o;
                o.x = xv.x & ~prmt(m, m, 0x8888);
                o.y = xv.y & ~prmt(m, m, 0x9999);
                o.z = xv.z & ~prmt(m, m, 0xAAAA);
                o.w = xv.w & ~prmt(m, m, 0xBBBB);
                __stcs(&xo[(size_t)(y0 + y + j) * WORDS + w_idx], o); // evict-first
            }

            vsum -= (hist >> 6) & 0x01010101u;            // drop row y+j-3
        }
        pq0 = nq0;
        pq1 = nq1;
    }
}

__global__ void __launch_bounds__(288, 5)
backedge_kernel(const uint4* __restrict__ x, uint4* __restrict__ out)
{
    const int lane = threadIdx.x & 31;
    const int warp = threadIdx.x >> 5;               // 0..8
    const int w_idx = warp * 30 + lane - 1;          // output word (-1..270)
    const int l_idx = min(max(w_idx, 0), WORDS - 1); // clamped load word
    const bool active = (lane >= 1) && (lane <= 30) && (w_idx < WORDS);
    const bool ledge  = (w_idx == 0);
    const bool redge  = (w_idx == WORDS - 1);

    const int y0 = blockIdx.x * HB;
    const size_t off = (size_t)blockIdx.y * (size_t)W * WORDS;
    const uint4* __restrict__ xi = x + off;
    uint4* __restrict__ xo = out + off;

    // loads (incl. 2-row over-prefetch) span rows y0-3 .. y0+HB+4
    if (y0 - 3 < 0 || y0 + HB + 4 > W - 1)
        run_band<true >(xi, xo, y0, w_idx, l_idx, active, ledge, redge);
    else
        run_band<false>(xi, xo, y0, w_idx, l_idx, active, ledge, redge);
}

extern "C" void kernel_launch(void* const* d_in, const int* in_sizes, int n_in,
                              void* d_out, int out_size)
{
    const uint4* x = (const uint4*)d_in[0];
    uint4* o = (uint4*)d_out;
    const int nimg = in_sizes[0] / (W * W);   // 48 planes
    dim3 grid(W / HB, nimg);
    backedge_kernel<<<grid, 288>>>(x, o);
}